// round 14
// baseline (speedup 1.0000x reference)
#include <cuda_runtime.h>
#include <cuda_fp16.h>

#define NN 256
#define SS 64
#define BB 1024
#define UNFOLDS 12
#define FAST_STEPS 11          // steps 0..10 sparse f16x2; step 11 sparse fp32
#define TB 7                   // batches per CTA (147 CTAs cover 1024 with clamp)
#define GRID 147
#define NGRP 4                 // groups per CTA
#define CAP 192                // compacted-slot capacity per j

// Scratch (device globals — no allocations allowed).
__device__ uint4  g_cpar[CAP * NN];         // [slot][j] {a2dup, b2dup, we2dup, wa2dup} f16x2
__device__ float4 g_cparf[CAP * NN];        // [slot][j] {a, b, we, |we|} f32
__device__ unsigned char g_cidxT[NN * CAP]; // [j][slot] pre-neuron index
__device__ int    g_cntmax;                 // max active count over j
__device__ int    g_nblk;                   // 2-slot blocks per group (runtime)
__device__ float4 g_sparams[SS * NN];       // sensory {a, b, we, wsp} f32
__device__ float  g_sum_hw[NN];
__device__ float  g_sum_hwe[NN];
__device__ float  g_cmt[NN];
__device__ float  g_gl[NN];
__device__ float  g_gv[NN];

__device__ __forceinline__ float tanh_fast(float x) {
    float t;
    asm("tanh.approx.f32 %0, %1;" : "=f"(t) : "f"(x));
    return t;
}

__device__ __forceinline__ float softplus_f(float x) {
    return log1pf(expf(x));
}

// One compacted slot (one active pre-neuron i), batch-pairs (01,23,45,6pad):
//   arg2 = a2dup*vpair + b2dup (HFMA2); t = tanh.f16x2 (2 batches per XU op)
//   num2[p] += we2dup*t ; den2[p] += wa2dup*t (f16 partials, folded every 4 slots)
__device__ __forceinline__ void proc_slot2(uint4 vv, uint4 pq,
                                           unsigned* num2, unsigned* den2) {
    unsigned a, t;
    asm("fma.rn.f16x2 %0, %1, %2, %3;" : "=r"(a) : "r"(pq.x), "r"(vv.x), "r"(pq.y));
    asm("tanh.approx.f16x2 %0, %1;" : "=r"(t) : "r"(a));
    asm("fma.rn.f16x2 %0, %1, %2, %0;" : "+r"(num2[0]) : "r"(pq.z), "r"(t));
    asm("fma.rn.f16x2 %0, %1, %2, %0;" : "+r"(den2[0]) : "r"(pq.w), "r"(t));
    asm("fma.rn.f16x2 %0, %1, %2, %3;" : "=r"(a) : "r"(pq.x), "r"(vv.y), "r"(pq.y));
    asm("tanh.approx.f16x2 %0, %1;" : "=r"(t) : "r"(a));
    asm("fma.rn.f16x2 %0, %1, %2, %0;" : "+r"(num2[1]) : "r"(pq.z), "r"(t));
    asm("fma.rn.f16x2 %0, %1, %2, %0;" : "+r"(den2[1]) : "r"(pq.w), "r"(t));
    asm("fma.rn.f16x2 %0, %1, %2, %3;" : "=r"(a) : "r"(pq.x), "r"(vv.z), "r"(pq.y));
    asm("tanh.approx.f16x2 %0, %1;" : "=r"(t) : "r"(a));
    asm("fma.rn.f16x2 %0, %1, %2, %0;" : "+r"(num2[2]) : "r"(pq.z), "r"(t));
    asm("fma.rn.f16x2 %0, %1, %2, %0;" : "+r"(den2[2]) : "r"(pq.w), "r"(t));
    asm("fma.rn.f16x2 %0, %1, %2, %3;" : "=r"(a) : "r"(pq.x), "r"(vv.w), "r"(pq.y));
    asm("tanh.approx.f16x2 %0, %1;" : "=r"(t) : "r"(a));
    asm("fma.rn.f16x2 %0, %1, %2, %0;" : "+r"(num2[3]) : "r"(pq.z), "r"(t));
    asm("fma.rn.f16x2 %0, %1, %2, %0;" : "+r"(den2[3]) : "r"(pq.w), "r"(t));
}

__device__ __forceinline__ void fold2(unsigned h2, float& alo, float& ahi) {
    float lo, hi;
    asm("{ .reg .b16 l, h;\n\t"
        "  mov.b32 {l, h}, %2;\n\t"
        "  cvt.f32.f16 %0, l;\n\t"
        "  cvt.f32.f16 %1, h; }"
        : "=f"(lo), "=f"(hi) : "r"(h2));
    alo += lo;
    ahi += hi;
}
__device__ __forceinline__ void fold_lo(unsigned h2, float& alo) {
    float lo;
    asm("{ .reg .b16 l, h;\n\t"
        "  mov.b32 {l, h}, %1;\n\t"
        "  cvt.f32.f16 %0, l; }"
        : "=f"(lo) : "r"(h2));
    alo += lo;
}

// ---------------------------------------------------------------------------
// Parallel per-j compaction: one block per j, ballot + warp-prefix.
// sigmoid(s*(v-m)) = 0.5*(1 + tanh(0.5*s*v - 0.5*s*m)); hw = 0.5*softplus(w)
// (mask=1 on kept slots); hwe = hw*erev, erev=±1.
// ---------------------------------------------------------------------------
__global__ void k_compact(const float* __restrict__ w, const float* __restrict__ sigma,
                          const float* __restrict__ mu, const float* __restrict__ erev,
                          const float* __restrict__ mask) {
    int j = blockIdx.x, i = threadIdx.x;
    int lane = i & 31, wid = i >> 5;
    int x = i * NN + j;
    bool act = (mask[x] != 0.f);
    unsigned bal = __ballot_sync(0xFFFFFFFFu, act);
    int rank = __popc(bal & ((1u << lane) - 1u));
    __shared__ int woff[9];
    if (lane == 0) woff[wid + 1] = __popc(bal);
    __syncthreads();
    if (i == 0) {
        woff[0] = 0;
        for (int k = 1; k <= 8; k++) woff[k] += woff[k - 1];
        atomicMax(&g_cntmax, woff[8]);
    }
    __syncthreads();
    int cnt = woff[8];
    if (act) {
        int slot = woff[wid] + rank;
        float a  = 0.5f * sigma[x];
        float b  = -a * mu[x];
        float hw = 0.5f * softplus_f(w[x]);
        float we = hw * erev[x];
        __half2 A  = __half2half2(__float2half_rn(a));
        __half2 Bv = __half2half2(__float2half_rn(b));
        __half2 W  = __half2half2(__float2half_rn(we));
        __half2 Wa = __half2half2(__float2half_rn(hw));
        uint4 pq;
        pq.x = *reinterpret_cast<unsigned*>(&A);
        pq.y = *reinterpret_cast<unsigned*>(&Bv);
        pq.z = *reinterpret_cast<unsigned*>(&W);
        pq.w = *reinterpret_cast<unsigned*>(&Wa);
        g_cpar[slot * NN + j]  = pq;
        g_cparf[slot * NN + j] = make_float4(a, b, we, hw);
        g_cidxT[j * CAP + slot] = (unsigned char)i;
    }
    // zero-pad remaining slots (contribute exactly 0)
    for (int s = cnt + i; s < CAP; s += NN) {
        g_cpar[s * NN + j]  = make_uint4(0u, 0u, 0u, 0u);
        g_cparf[s * NN + j] = make_float4(0.f, 0.f, 0.f, 0.f);
        g_cidxT[j * CAP + s] = 0;
    }
}

__global__ void k_final() {
    int c = g_cntmax;
    int nb = (c + NGRP * 2 - 1) / (NGRP * 2);   // 2-slot blocks per group
    if (nb < 1) nb = 1;
    if (nb > CAP / (NGRP * 2)) nb = CAP / (NGRP * 2);
    g_nblk = nb;
}

__global__ void k_sprep(const float* __restrict__ sw, const float* __restrict__ ssig,
                        const float* __restrict__ smu, const float* __restrict__ serev,
                        const float* __restrict__ smask) {
    int s = blockIdx.x, j = threadIdx.x;
    int idx = s * NN + j;
    float wsp = softplus_f(sw[idx]) * smask[idx];
    float a   = 0.5f * ssig[idx];
    g_sparams[idx] = make_float4(a, -a * smu[idx], wsp * serev[idx], wsp);
}

// Column sums from the compacted f32 table + per-neuron scalars.
__global__ void k_colsums(const float* __restrict__ gleak, const float* __restrict__ vleak,
                          const float* __restrict__ cm) {
    int j = threadIdx.x;
    float shw = 0.f, shwe = 0.f;
    for (int s = 0; s < CAP; s++) {
        float4 e = g_cparf[s * NN + j];
        shwe += e.z;
        shw  += e.w;
    }
    g_sum_hw[j]  = shw;
    g_sum_hwe[j] = shwe;
    float gl = softplus_f(gleak[j]);
    g_gl[j]  = gl;
    g_gv[j]  = gl * vleak[j];
    g_cmt[j] = softplus_f(cm[j]) * (float)UNFOLDS;
}

// SMEM layout (dynamic)
#define SM_VFT  0                                // NN*8*4  = 8192 (f32 transposed state)
#define SM_VHT  (NN * 8 * 4)                     // NN*8*2  = 4096
#define SM_XIN  (SM_VHT + NN * 8 * 2)            // TB*SS*4 = 1792
#define SM_PART (SM_XIN + TB * SS * 4)           // 4*7*256*8 = 57344
#define SM_TOTAL (SM_PART + NGRP * TB * NN * 8)  // 71424

// ---------------------------------------------------------------------------
// Main: 147 CTAs x 1024 threads = 4 groups of 256 j-threads.
// Fast steps: group ig processes compacted slots [ig*2*nblk, (ig+1)*2*nblk)
// for ALL 7 batches via transposed v gathers (batch-paired f16x2 tanh),
// with one-block param prefetch. Final step: SAME slot list in fp32.
// ---------------------------------------------------------------------------
__global__ void __launch_bounds__(1024, 1) k_main(const float* __restrict__ inputs,
                                                  const float* __restrict__ state,
                                                  float* __restrict__ out) {
    extern __shared__ char smem[];
    float*  v_fT           = reinterpret_cast<float*>(smem + SM_VFT);    // [NN][8]
    __half* v_hT           = reinterpret_cast<__half*>(smem + SM_VHT);   // [NN][8]
    float  (*xin)[SS]      = reinterpret_cast<float (*)[SS]>(smem + SM_XIN);
    float2 (*part)[TB][NN] = reinterpret_cast<float2 (*)[TB][NN]>(smem + SM_PART);

    int tid = threadIdx.x;
    int ig  = tid >> 8;          // 0..3
    int j   = tid & 255;
    int b0  = blockIdx.x * TB;
    int ob      = ig * 2;
    int own_cnt = (ig == 3) ? 1 : 2;

    if (tid < TB * SS) xin[tid >> 6][tid & 63] = inputs[min(b0 * SS + tid, BB * SS - 1)];
    for (int idx = tid; idx < TB * NN; idx += 1024) {
        float v = state[min(b0 * NN + idx, BB * NN - 1)];
        int bb = idx >> 8, jj = idx & 255;
        v_fT[jj * 8 + bb] = v;
        v_hT[jj * 8 + bb] = __float2half_rn(v);
    }
    if (tid < NN) {                       // pad batch 7
        v_fT[tid * 8 + 7] = 0.f;
        v_hT[tid * 8 + 7] = __float2half_rn(0.f);
    }
    __syncthreads();

    // --- sensory pass (step-invariant) for owned batches (<=2) ---
    float ncr[2], dcr[2];
    {
        float sn[2] = {0.f, 0.f}, sd[2] = {0.f, 0.f};
        #pragma unroll 2
        for (int s = 0; s < SS; s++) {
            float4 q = g_sparams[s * NN + j];
            #pragma unroll
            for (int k = 0; k < 2; k++) {
                int bx = ob + min(k, own_cnt - 1);
                float t  = tanh_fast(fmaf(q.x, xin[bx][s], q.y));
                float sg = fmaf(0.5f, t, 0.5f);
                sn[k] = fmaf(q.z, sg, sn[k]);
                sd[k] = fmaf(q.w, sg, sd[k]);
            }
        }
        float gv = g_gv[j], she = g_sum_hwe[j], gl = g_gl[j], shw = g_sum_hw[j];
        float cmt0 = g_cmt[j];
        #pragma unroll
        for (int k = 0; k < 2; k++) {
            ncr[k] = gv + she + sn[k];
            dcr[k] = cmt0 + gl + shw + sd[k] + 1e-8f;
        }
    }
    float cmt = g_cmt[j];
    int nblk = g_nblk;                        // uniform runtime bound
    int sbase = ig * 2 * nblk;                // this group's first slot
    const unsigned char* CI = g_cidxT + j * CAP;
    const uint4*  CP  = g_cpar  + j;
    const float4* CPF = g_cparf + j;

    for (int step = 0; step < UNFOLDS; step++) {
        float numf[TB], denf[TB];
        #pragma unroll
        for (int b = 0; b < TB; b++) { numf[b] = 0.f; denf[b] = 0.f; }

        if (step < FAST_STEPS) {
            // ---------- sparse f16x2 path with one-block prefetch ----------
            unsigned num2[4] = {0u, 0u, 0u, 0u};
            unsigned den2[4] = {0u, 0u, 0u, 0u};
            uint4 p0 = CP[(sbase    ) * NN];
            uint4 p1 = CP[(sbase + 1) * NN];
            for (int blk = 0; blk < nblk; blk++) {
                int s0 = sbase + blk * 2;
                uchar2 ii = *reinterpret_cast<const uchar2*>(CI + s0);
                uint4 c0 = p0, c1 = p1;
                int sn = min(s0 + 2, CAP - 2);           // clamped prefetch
                p0 = CP[(sn    ) * NN];
                p1 = CP[(sn + 1) * NN];
                uint4 v0 = *reinterpret_cast<const uint4*>(v_hT + (int)ii.x * 8);
                uint4 v1 = *reinterpret_cast<const uint4*>(v_hT + (int)ii.y * 8);
                proc_slot2(v0, c0, num2, den2);
                proc_slot2(v1, c1, num2, den2);
                if ((blk & 1) || (blk == nblk - 1)) {
                    // fold 4-slot f16 partials to f32 (batch 7 = pad dropped)
                    fold2(num2[0], numf[0], numf[1]);
                    fold2(num2[1], numf[2], numf[3]);
                    fold2(num2[2], numf[4], numf[5]);
                    fold_lo(num2[3], numf[6]);
                    fold2(den2[0], denf[0], denf[1]);
                    fold2(den2[1], denf[2], denf[3]);
                    fold2(den2[2], denf[4], denf[5]);
                    fold_lo(den2[3], denf[6]);
                    #pragma unroll
                    for (int p = 0; p < 4; p++) { num2[p] = 0u; den2[p] = 0u; }
                }
            }
        } else {
            // ---------- sparse fp32 path (last step, same slot list) ----------
            for (int blk = 0; blk < nblk; blk++) {
                int s0 = sbase + blk * 2;
                uchar2 ii = *reinterpret_cast<const uchar2*>(CI + s0);
                #pragma unroll
                for (int h = 0; h < 2; h++) {
                    int slot = s0 + h;
                    int idx  = h ? (int)ii.y : (int)ii.x;
                    float4 pf = CPF[slot * NN];
                    float4 va = *reinterpret_cast<const float4*>(v_fT + idx * 8);
                    float4 vb = *reinterpret_cast<const float4*>(v_fT + idx * 8 + 4);
                    float t0 = tanh_fast(fmaf(pf.x, va.x, pf.y));
                    float t1 = tanh_fast(fmaf(pf.x, va.y, pf.y));
                    float t2 = tanh_fast(fmaf(pf.x, va.z, pf.y));
                    float t3 = tanh_fast(fmaf(pf.x, va.w, pf.y));
                    float t4 = tanh_fast(fmaf(pf.x, vb.x, pf.y));
                    float t5 = tanh_fast(fmaf(pf.x, vb.y, pf.y));
                    float t6 = tanh_fast(fmaf(pf.x, vb.z, pf.y));
                    numf[0] = fmaf(pf.z, t0, numf[0]); denf[0] = fmaf(pf.w, t0, denf[0]);
                    numf[1] = fmaf(pf.z, t1, numf[1]); denf[1] = fmaf(pf.w, t1, denf[1]);
                    numf[2] = fmaf(pf.z, t2, numf[2]); denf[2] = fmaf(pf.w, t2, denf[2]);
                    numf[3] = fmaf(pf.z, t3, numf[3]); denf[3] = fmaf(pf.w, t3, denf[3]);
                    numf[4] = fmaf(pf.z, t4, numf[4]); denf[4] = fmaf(pf.w, t4, denf[4]);
                    numf[5] = fmaf(pf.z, t5, numf[5]); denf[5] = fmaf(pf.w, t5, denf[5]);
                    numf[6] = fmaf(pf.z, t6, numf[6]); denf[6] = fmaf(pf.w, t6, denf[6]);
                }
            }
        }

        #pragma unroll
        for (int b = 0; b < TB; b++)
            part[ig][b][j] = make_float2(numf[b], denf[b]);
        __syncthreads();

        #pragma unroll
        for (int k = 0; k < 2; k++) {
            if (k < own_cnt) {
                int b = ob + k;
                float2 p0 = part[0][b][j];
                float2 p1 = part[1][b][j];
                float2 p2 = part[2][b][j];
                float2 p3 = part[3][b][j];
                float n = (p0.x + p1.x) + (p2.x + p3.x);
                float d = (p0.y + p1.y) + (p2.y + p3.y);
                float vn = (fmaf(cmt, v_fT[j * 8 + b], ncr[k]) + n) / (d + dcr[k]);
                v_fT[j * 8 + b] = vn;
                v_hT[j * 8 + b] = __float2half_rn(vn);
            }
        }
        __syncthreads();
    }

    #pragma unroll
    for (int k = 0; k < 2; k++) {
        if (k < own_cnt) {
            int b = ob + k;
            if (b0 + b < BB) out[(b0 + b) * NN + j] = v_fT[j * 8 + b];
        }
    }
}

extern "C" void kernel_launch(void* const* d_in, const int* in_sizes, int n_in,
                              void* d_out, int out_size) {
    const float* inputs = (const float*)d_in[0];
    const float* state  = (const float*)d_in[1];
    const float* gleak  = (const float*)d_in[2];
    const float* vleak  = (const float*)d_in[3];
    const float* cm     = (const float*)d_in[4];
    const float* w      = (const float*)d_in[5];
    const float* sigma  = (const float*)d_in[6];
    const float* mu     = (const float*)d_in[7];
    const float* erev   = (const float*)d_in[8];
    const float* sw     = (const float*)d_in[9];
    const float* ssig   = (const float*)d_in[10];
    const float* smu    = (const float*)d_in[11];
    const float* serev  = (const float*)d_in[12];
    const float* mask   = (const float*)d_in[13];
    const float* smask  = (const float*)d_in[14];
    float* out = (float*)d_out;

    cudaFuncSetAttribute(k_main, cudaFuncAttributeMaxDynamicSharedMemorySize, SM_TOTAL);

    k_compact<<<NN, NN>>>(w, sigma, mu, erev, mask);
    k_final  <<<1, 1>>>();
    k_sprep  <<<SS, NN>>>(sw, ssig, smu, serev, smask);
    k_colsums<<<1,  NN>>>(gleak, vleak, cm);
    k_main   <<<GRID, 1024, SM_TOTAL>>>(inputs, state, out);
}

// round 15
// speedup vs baseline: 1.0521x; 1.0521x over previous
#include <cuda_runtime.h>
#include <cuda_fp16.h>

#define NN 256
#define SS 64
#define BB 1024
#define UNFOLDS 12
#define FAST_STEPS 11          // steps 0..10 sparse f16x2; step 11 sparse fp32
#define TB 7                   // batches per CTA (147 CTAs cover 1024 with clamp)
#define GRID 147
#define NGRP 4                 // groups per CTA
#define CAP 192                // compacted-slot capacity per j
#define BPG (CAP / (NGRP * 2)) // max 2-slot blocks per group

// Scratch (device globals — no allocations allowed).
__device__ uint4  g_cpar[CAP * NN];         // [slot][j] {a2dup, b2dup, we2dup, wa2dup} f16x2
__device__ float4 g_cparf[CAP * NN];        // [slot][j] {a, b, we, |we|} f32
__device__ unsigned char g_cidxT[NN * CAP]; // [j][slot] pre-neuron index
__device__ int    g_cntmax;                 // max active count over j
__device__ float4 g_sparams[SS * NN];       // sensory {a, b, we, wsp} f32
__device__ float  g_sum_hw[NN];
__device__ float  g_sum_hwe[NN];
__device__ float  g_cmt[NN];
__device__ float  g_gl[NN];
__device__ float  g_gv[NN];

__device__ __forceinline__ float tanh_fast(float x) {
    float t;
    asm("tanh.approx.f32 %0, %1;" : "=f"(t) : "f"(x));
    return t;
}

__device__ __forceinline__ float softplus_f(float x) {
    return log1pf(expf(x));
}

// One compacted slot (one active pre-neuron i), batch-pairs (01,23,45,6pad):
//   arg2 = a2dup*vpair + b2dup (HFMA2); t = tanh.f16x2 (2 batches per XU op)
//   num2[p] += we2dup*t ; den2[p] += wa2dup*t (f16 partials, folded every 4 slots)
__device__ __forceinline__ void proc_slot2(uint4 vv, uint4 pq,
                                           unsigned* num2, unsigned* den2) {
    unsigned a, t;
    asm("fma.rn.f16x2 %0, %1, %2, %3;" : "=r"(a) : "r"(pq.x), "r"(vv.x), "r"(pq.y));
    asm("tanh.approx.f16x2 %0, %1;" : "=r"(t) : "r"(a));
    asm("fma.rn.f16x2 %0, %1, %2, %0;" : "+r"(num2[0]) : "r"(pq.z), "r"(t));
    asm("fma.rn.f16x2 %0, %1, %2, %0;" : "+r"(den2[0]) : "r"(pq.w), "r"(t));
    asm("fma.rn.f16x2 %0, %1, %2, %3;" : "=r"(a) : "r"(pq.x), "r"(vv.y), "r"(pq.y));
    asm("tanh.approx.f16x2 %0, %1;" : "=r"(t) : "r"(a));
    asm("fma.rn.f16x2 %0, %1, %2, %0;" : "+r"(num2[1]) : "r"(pq.z), "r"(t));
    asm("fma.rn.f16x2 %0, %1, %2, %0;" : "+r"(den2[1]) : "r"(pq.w), "r"(t));
    asm("fma.rn.f16x2 %0, %1, %2, %3;" : "=r"(a) : "r"(pq.x), "r"(vv.z), "r"(pq.y));
    asm("tanh.approx.f16x2 %0, %1;" : "=r"(t) : "r"(a));
    asm("fma.rn.f16x2 %0, %1, %2, %0;" : "+r"(num2[2]) : "r"(pq.z), "r"(t));
    asm("fma.rn.f16x2 %0, %1, %2, %0;" : "+r"(den2[2]) : "r"(pq.w), "r"(t));
    asm("fma.rn.f16x2 %0, %1, %2, %3;" : "=r"(a) : "r"(pq.x), "r"(vv.w), "r"(pq.y));
    asm("tanh.approx.f16x2 %0, %1;" : "=r"(t) : "r"(a));
    asm("fma.rn.f16x2 %0, %1, %2, %0;" : "+r"(num2[3]) : "r"(pq.z), "r"(t));
    asm("fma.rn.f16x2 %0, %1, %2, %0;" : "+r"(den2[3]) : "r"(pq.w), "r"(t));
}

__device__ __forceinline__ void fold2(unsigned h2, float& alo, float& ahi) {
    float lo, hi;
    asm("{ .reg .b16 l, h;\n\t"
        "  mov.b32 {l, h}, %2;\n\t"
        "  cvt.f32.f16 %0, l;\n\t"
        "  cvt.f32.f16 %1, h; }"
        : "=f"(lo), "=f"(hi) : "r"(h2));
    alo += lo;
    ahi += hi;
}
__device__ __forceinline__ void fold_lo(unsigned h2, float& alo) {
    float lo;
    asm("{ .reg .b16 l, h;\n\t"
        "  mov.b32 {l, h}, %1;\n\t"
        "  cvt.f32.f16 %0, l; }"
        : "=f"(lo) : "r"(h2));
    alo += lo;
}

// ---------------------------------------------------------------------------
// Parallel per-j compaction + fused column sums + per-neuron scalars.
// One block per j, ballot + warp-prefix; shfl-tree reduction for sums.
// sigmoid(s*(v-m)) = 0.5*(1 + tanh(0.5*s*v - 0.5*s*m)); hw = 0.5*softplus(w)
// (mask=1 on kept slots); hwe = hw*erev, erev=±1.
// ---------------------------------------------------------------------------
__global__ void k_compact(const float* __restrict__ w, const float* __restrict__ sigma,
                          const float* __restrict__ mu, const float* __restrict__ erev,
                          const float* __restrict__ mask,
                          const float* __restrict__ gleak, const float* __restrict__ vleak,
                          const float* __restrict__ cm) {
    int j = blockIdx.x, i = threadIdx.x;
    int lane = i & 31, wid = i >> 5;
    int x = i * NN + j;
    bool act = (mask[x] != 0.f);
    unsigned bal = __ballot_sync(0xFFFFFFFFu, act);
    int rank = __popc(bal & ((1u << lane) - 1u));
    __shared__ int woff[9];
    __shared__ float swh[8], swe[8];
    if (lane == 0) woff[wid + 1] = __popc(bal);
    __syncthreads();
    if (i == 0) {
        woff[0] = 0;
        for (int k = 1; k <= 8; k++) woff[k] += woff[k - 1];
        atomicMax(&g_cntmax, woff[8]);
    }
    __syncthreads();
    int cnt = woff[8];

    float hw = 0.f, we = 0.f;
    if (act) {
        int slot = woff[wid] + rank;
        float a  = 0.5f * sigma[x];
        float b  = -a * mu[x];
        hw = 0.5f * softplus_f(w[x]);
        we = hw * erev[x];
        __half2 A  = __half2half2(__float2half_rn(a));
        __half2 Bv = __half2half2(__float2half_rn(b));
        __half2 W  = __half2half2(__float2half_rn(we));
        __half2 Wa = __half2half2(__float2half_rn(hw));
        uint4 pq;
        pq.x = *reinterpret_cast<unsigned*>(&A);
        pq.y = *reinterpret_cast<unsigned*>(&Bv);
        pq.z = *reinterpret_cast<unsigned*>(&W);
        pq.w = *reinterpret_cast<unsigned*>(&Wa);
        g_cpar[slot * NN + j]  = pq;
        g_cparf[slot * NN + j] = make_float4(a, b, we, hw);
        g_cidxT[j * CAP + slot] = (unsigned char)i;
    }

    // fused column sums: shfl-tree within warps, then 8-entry fold
    #pragma unroll
    for (int off = 16; off > 0; off >>= 1) {
        hw += __shfl_down_sync(0xFFFFFFFFu, hw, off);
        we += __shfl_down_sync(0xFFFFFFFFu, we, off);
    }
    if (lane == 0) { swh[wid] = hw; swe[wid] = we; }

    // zero-pad remaining slots (contribute exactly 0)
    for (int s = cnt + i; s < CAP; s += NN) {
        g_cpar[s * NN + j]  = make_uint4(0u, 0u, 0u, 0u);
        g_cparf[s * NN + j] = make_float4(0.f, 0.f, 0.f, 0.f);
        g_cidxT[j * CAP + s] = 0;
    }
    __syncthreads();
    if (i == 0) {
        float shw = 0.f, shwe = 0.f;
        #pragma unroll
        for (int k = 0; k < 8; k++) { shw += swh[k]; shwe += swe[k]; }
        g_sum_hw[j]  = shw;
        g_sum_hwe[j] = shwe;
        float gl = softplus_f(gleak[j]);
        g_gl[j]  = gl;
        g_gv[j]  = gl * vleak[j];
        g_cmt[j] = softplus_f(cm[j]) * (float)UNFOLDS;
    }
}

__global__ void k_sprep(const float* __restrict__ sw, const float* __restrict__ ssig,
                        const float* __restrict__ smu, const float* __restrict__ serev,
                        const float* __restrict__ smask) {
    int s = blockIdx.x, j = threadIdx.x;
    int idx = s * NN + j;
    float wsp = softplus_f(sw[idx]) * smask[idx];
    float a   = 0.5f * ssig[idx];
    g_sparams[idx] = make_float4(a, -a * smu[idx], wsp * serev[idx], wsp);
}

// SMEM layout (dynamic)
#define SM_VFT  0                                // NN*8*4  = 8192 (f32 transposed state)
#define SM_VHT  (NN * 8 * 4)                     // NN*8*2  = 4096
#define SM_XIN  (SM_VHT + NN * 8 * 2)            // TB*SS*4 = 1792
#define SM_PART (SM_XIN + TB * SS * 4)           // 4*7*256*8 = 57344
#define SM_TOTAL (SM_PART + NGRP * TB * NN * 8)  // 71424

// ---------------------------------------------------------------------------
// Main: 147 CTAs x 1024 threads = 4 groups of 256 j-threads.
// Fast steps: group ig processes compacted slots [ig*2*nblk, (ig+1)*2*nblk)
// for ALL 7 batches via transposed v gathers (batch-paired f16x2 tanh),
// with one-block param prefetch. Final step: SAME slot list in fp32.
// nblk derived inline from g_cntmax (uniform across all threads).
// ---------------------------------------------------------------------------
__global__ void __launch_bounds__(1024, 1) k_main(const float* __restrict__ inputs,
                                                  const float* __restrict__ state,
                                                  float* __restrict__ out) {
    extern __shared__ char smem[];
    float*  v_fT           = reinterpret_cast<float*>(smem + SM_VFT);    // [NN][8]
    __half* v_hT           = reinterpret_cast<__half*>(smem + SM_VHT);   // [NN][8]
    float  (*xin)[SS]      = reinterpret_cast<float (*)[SS]>(smem + SM_XIN);
    float2 (*part)[TB][NN] = reinterpret_cast<float2 (*)[TB][NN]>(smem + SM_PART);

    int tid = threadIdx.x;
    int ig  = tid >> 8;          // 0..3
    int j   = tid & 255;
    int b0  = blockIdx.x * TB;
    int ob      = ig * 2;
    int own_cnt = (ig == 3) ? 1 : 2;

    if (tid < TB * SS) xin[tid >> 6][tid & 63] = inputs[min(b0 * SS + tid, BB * SS - 1)];
    for (int idx = tid; idx < TB * NN; idx += 1024) {
        float v = state[min(b0 * NN + idx, BB * NN - 1)];
        int bb = idx >> 8, jj = idx & 255;
        v_fT[jj * 8 + bb] = v;
        v_hT[jj * 8 + bb] = __float2half_rn(v);
    }
    if (tid < NN) {                       // pad batch 7
        v_fT[tid * 8 + 7] = 0.f;
        v_hT[tid * 8 + 7] = __float2half_rn(0.f);
    }
    __syncthreads();

    // --- sensory pass (step-invariant) for owned batches (<=2) ---
    float ncr[2], dcr[2];
    {
        float sn[2] = {0.f, 0.f}, sd[2] = {0.f, 0.f};
        #pragma unroll 2
        for (int s = 0; s < SS; s++) {
            float4 q = g_sparams[s * NN + j];
            #pragma unroll
            for (int k = 0; k < 2; k++) {
                int bx = ob + min(k, own_cnt - 1);
                float t  = tanh_fast(fmaf(q.x, xin[bx][s], q.y));
                float sg = fmaf(0.5f, t, 0.5f);
                sn[k] = fmaf(q.z, sg, sn[k]);
                sd[k] = fmaf(q.w, sg, sd[k]);
            }
        }
        float gv = g_gv[j], she = g_sum_hwe[j], gl = g_gl[j], shw = g_sum_hw[j];
        float cmt0 = g_cmt[j];
        #pragma unroll
        for (int k = 0; k < 2; k++) {
            ncr[k] = gv + she + sn[k];
            dcr[k] = cmt0 + gl + shw + sd[k] + 1e-8f;
        }
    }
    float cmt = g_cmt[j];

    // nblk computed inline (uniform): 2-slot blocks per group
    int nblk;
    {
        int c = g_cntmax;
        nblk = (c + NGRP * 2 - 1) / (NGRP * 2);
        if (nblk < 1) nblk = 1;
        if (nblk > BPG) nblk = BPG;
    }
    int sbase = ig * 2 * nblk;                // this group's first slot
    const unsigned char* CI = g_cidxT + j * CAP;
    const uint4*  CP  = g_cpar  + j;
    const float4* CPF = g_cparf + j;

    for (int step = 0; step < UNFOLDS; step++) {
        float numf[TB], denf[TB];
        #pragma unroll
        for (int b = 0; b < TB; b++) { numf[b] = 0.f; denf[b] = 0.f; }

        if (step < FAST_STEPS) {
            // ---------- sparse f16x2 path with one-block prefetch ----------
            unsigned num2[4] = {0u, 0u, 0u, 0u};
            unsigned den2[4] = {0u, 0u, 0u, 0u};
            uint4 p0 = CP[(sbase    ) * NN];
            uint4 p1 = CP[(sbase + 1) * NN];
            for (int blk = 0; blk < nblk; blk++) {
                int s0 = sbase + blk * 2;
                uchar2 ii = *reinterpret_cast<const uchar2*>(CI + s0);
                uint4 c0 = p0, c1 = p1;
                int sn = min(s0 + 2, CAP - 2);           // clamped prefetch
                p0 = CP[(sn    ) * NN];
                p1 = CP[(sn + 1) * NN];
                uint4 v0 = *reinterpret_cast<const uint4*>(v_hT + (int)ii.x * 8);
                uint4 v1 = *reinterpret_cast<const uint4*>(v_hT + (int)ii.y * 8);
                proc_slot2(v0, c0, num2, den2);
                proc_slot2(v1, c1, num2, den2);
                if ((blk & 1) || (blk == nblk - 1)) {
                    // fold 4-slot f16 partials to f32 (batch 7 = pad dropped)
                    fold2(num2[0], numf[0], numf[1]);
                    fold2(num2[1], numf[2], numf[3]);
                    fold2(num2[2], numf[4], numf[5]);
                    fold_lo(num2[3], numf[6]);
                    fold2(den2[0], denf[0], denf[1]);
                    fold2(den2[1], denf[2], denf[3]);
                    fold2(den2[2], denf[4], denf[5]);
                    fold_lo(den2[3], denf[6]);
                    #pragma unroll
                    for (int p = 0; p < 4; p++) { num2[p] = 0u; den2[p] = 0u; }
                }
            }
        } else {
            // ---------- sparse fp32 path (last step, same slot list) ----------
            for (int blk = 0; blk < nblk; blk++) {
                int s0 = sbase + blk * 2;
                uchar2 ii = *reinterpret_cast<const uchar2*>(CI + s0);
                #pragma unroll
                for (int h = 0; h < 2; h++) {
                    int slot = s0 + h;
                    int idx  = h ? (int)ii.y : (int)ii.x;
                    float4 pf = CPF[slot * NN];
                    float4 va = *reinterpret_cast<const float4*>(v_fT + idx * 8);
                    float4 vb = *reinterpret_cast<const float4*>(v_fT + idx * 8 + 4);
                    float t0 = tanh_fast(fmaf(pf.x, va.x, pf.y));
                    float t1 = tanh_fast(fmaf(pf.x, va.y, pf.y));
                    float t2 = tanh_fast(fmaf(pf.x, va.z, pf.y));
                    float t3 = tanh_fast(fmaf(pf.x, va.w, pf.y));
                    float t4 = tanh_fast(fmaf(pf.x, vb.x, pf.y));
                    float t5 = tanh_fast(fmaf(pf.x, vb.y, pf.y));
                    float t6 = tanh_fast(fmaf(pf.x, vb.z, pf.y));
                    numf[0] = fmaf(pf.z, t0, numf[0]); denf[0] = fmaf(pf.w, t0, denf[0]);
                    numf[1] = fmaf(pf.z, t1, numf[1]); denf[1] = fmaf(pf.w, t1, denf[1]);
                    numf[2] = fmaf(pf.z, t2, numf[2]); denf[2] = fmaf(pf.w, t2, denf[2]);
                    numf[3] = fmaf(pf.z, t3, numf[3]); denf[3] = fmaf(pf.w, t3, denf[3]);
                    numf[4] = fmaf(pf.z, t4, numf[4]); denf[4] = fmaf(pf.w, t4, denf[4]);
                    numf[5] = fmaf(pf.z, t5, numf[5]); denf[5] = fmaf(pf.w, t5, denf[5]);
                    numf[6] = fmaf(pf.z, t6, numf[6]); denf[6] = fmaf(pf.w, t6, denf[6]);
                }
            }
        }

        #pragma unroll
        for (int b = 0; b < TB; b++)
            part[ig][b][j] = make_float2(numf[b], denf[b]);
        __syncthreads();

        #pragma unroll
        for (int k = 0; k < 2; k++) {
            if (k < own_cnt) {
                int b = ob + k;
                float2 p0 = part[0][b][j];
                float2 p1 = part[1][b][j];
                float2 p2 = part[2][b][j];
                float2 p3 = part[3][b][j];
                float n = (p0.x + p1.x) + (p2.x + p3.x);
                float d = (p0.y + p1.y) + (p2.y + p3.y);
                float vn = (fmaf(cmt, v_fT[j * 8 + b], ncr[k]) + n) / (d + dcr[k]);
                v_fT[j * 8 + b] = vn;
                v_hT[j * 8 + b] = __float2half_rn(vn);
            }
        }
        __syncthreads();
    }

    #pragma unroll
    for (int k = 0; k < 2; k++) {
        if (k < own_cnt) {
            int b = ob + k;
            if (b0 + b < BB) out[(b0 + b) * NN + j] = v_fT[j * 8 + b];
        }
    }
}

extern "C" void kernel_launch(void* const* d_in, const int* in_sizes, int n_in,
                              void* d_out, int out_size) {
    const float* inputs = (const float*)d_in[0];
    const float* state  = (const float*)d_in[1];
    const float* gleak  = (const float*)d_in[2];
    const float* vleak  = (const float*)d_in[3];
    const float* cm     = (const float*)d_in[4];
    const float* w      = (const float*)d_in[5];
    const float* sigma  = (const float*)d_in[6];
    const float* mu     = (const float*)d_in[7];
    const float* erev   = (const float*)d_in[8];
    const float* sw     = (const float*)d_in[9];
    const float* ssig   = (const float*)d_in[10];
    const float* smu    = (const float*)d_in[11];
    const float* serev  = (const float*)d_in[12];
    const float* mask   = (const float*)d_in[13];
    const float* smask  = (const float*)d_in[14];
    float* out = (float*)d_out;

    cudaFuncSetAttribute(k_main, cudaFuncAttributeMaxDynamicSharedMemorySize, SM_TOTAL);

    k_compact<<<NN, NN>>>(w, sigma, mu, erev, mask, gleak, vleak, cm);
    k_sprep  <<<SS, NN>>>(sw, ssig, smu, serev, smask);
    k_main   <<<GRID, 1024, SM_TOTAL>>>(inputs, state, out);
}

// round 16
// speedup vs baseline: 1.0806x; 1.0271x over previous
#include <cuda_runtime.h>
#include <cuda_fp16.h>

#define NN 256
#define SS 64
#define BB 1024
#define UNFOLDS 12
#define FAST_STEPS 11          // steps 0..10 sparse f16x2; step 11 sparse fp32
#define TB 7                   // batches per CTA (147 CTAs cover 1024 with clamp)
#define GRID 147
#define NGRP 4                 // groups per CTA
#define CAP 192                // compacted-slot capacity per j
#define BPG (CAP / (NGRP * 2)) // max 2-slot blocks per group

// Scratch (device globals — no allocations allowed).
__device__ uint4  g_cpar[CAP * NN];         // [slot][j] {a2dup, b2dup, we2dup, wa2dup} f16x2
__device__ float4 g_cparf[CAP * NN];        // [slot][j] {a, b, we, |we|} f32
__device__ unsigned char g_cidxT[NN * CAP]; // [j][slot] pre-neuron index
__device__ int    g_cntmax;                 // max active count over j
__device__ float4 g_sparams[SS * NN];       // sensory {a, b, we, wsp} f32
__device__ float  g_sum_hw[NN];
__device__ float  g_sum_hwe[NN];
__device__ float  g_cmt[NN];
__device__ float  g_gl[NN];
__device__ float  g_gv[NN];

__device__ __forceinline__ float tanh_fast(float x) {
    float t;
    asm("tanh.approx.f32 %0, %1;" : "=f"(t) : "f"(x));
    return t;
}

__device__ __forceinline__ float softplus_f(float x) {
    return log1pf(expf(x));
}

// One compacted slot (one active pre-neuron i), batch-pairs (01,23,45,6pad):
//   arg2 = a2dup*vpair + b2dup (HFMA2); t = tanh.f16x2 (2 batches per XU op)
//   num2[p] += we2dup*t ; den2[p] += wa2dup*t (f16 partials, folded every 4 slots)
__device__ __forceinline__ void proc_slot2(uint4 vv, uint4 pq,
                                           unsigned* num2, unsigned* den2) {
    unsigned a, t;
    asm("fma.rn.f16x2 %0, %1, %2, %3;" : "=r"(a) : "r"(pq.x), "r"(vv.x), "r"(pq.y));
    asm("tanh.approx.f16x2 %0, %1;" : "=r"(t) : "r"(a));
    asm("fma.rn.f16x2 %0, %1, %2, %0;" : "+r"(num2[0]) : "r"(pq.z), "r"(t));
    asm("fma.rn.f16x2 %0, %1, %2, %0;" : "+r"(den2[0]) : "r"(pq.w), "r"(t));
    asm("fma.rn.f16x2 %0, %1, %2, %3;" : "=r"(a) : "r"(pq.x), "r"(vv.y), "r"(pq.y));
    asm("tanh.approx.f16x2 %0, %1;" : "=r"(t) : "r"(a));
    asm("fma.rn.f16x2 %0, %1, %2, %0;" : "+r"(num2[1]) : "r"(pq.z), "r"(t));
    asm("fma.rn.f16x2 %0, %1, %2, %0;" : "+r"(den2[1]) : "r"(pq.w), "r"(t));
    asm("fma.rn.f16x2 %0, %1, %2, %3;" : "=r"(a) : "r"(pq.x), "r"(vv.z), "r"(pq.y));
    asm("tanh.approx.f16x2 %0, %1;" : "=r"(t) : "r"(a));
    asm("fma.rn.f16x2 %0, %1, %2, %0;" : "+r"(num2[2]) : "r"(pq.z), "r"(t));
    asm("fma.rn.f16x2 %0, %1, %2, %0;" : "+r"(den2[2]) : "r"(pq.w), "r"(t));
    asm("fma.rn.f16x2 %0, %1, %2, %3;" : "=r"(a) : "r"(pq.x), "r"(vv.w), "r"(pq.y));
    asm("tanh.approx.f16x2 %0, %1;" : "=r"(t) : "r"(a));
    asm("fma.rn.f16x2 %0, %1, %2, %0;" : "+r"(num2[3]) : "r"(pq.z), "r"(t));
    asm("fma.rn.f16x2 %0, %1, %2, %0;" : "+r"(den2[3]) : "r"(pq.w), "r"(t));
}

__device__ __forceinline__ void fold2(unsigned h2, float& alo, float& ahi) {
    float lo, hi;
    asm("{ .reg .b16 l, h;\n\t"
        "  mov.b32 {l, h}, %2;\n\t"
        "  cvt.f32.f16 %0, l;\n\t"
        "  cvt.f32.f16 %1, h; }"
        : "=f"(lo), "=f"(hi) : "r"(h2));
    alo += lo;
    ahi += hi;
}
__device__ __forceinline__ void fold_lo(unsigned h2, float& alo) {
    float lo;
    asm("{ .reg .b16 l, h;\n\t"
        "  mov.b32 {l, h}, %1;\n\t"
        "  cvt.f32.f16 %0, l; }"
        : "=f"(lo) : "r"(h2));
    alo += lo;
}

// ---------------------------------------------------------------------------
// Parallel per-j compaction with BANK-GROUP SCHEDULING + fused column sums,
// per-neuron scalars, and sensory table. One block per j.
// Slots are ordered by key = ((i&7) - (j&7)) & 7 so that, in k_main, the 32
// lanes of a warp (consecutive j) hit all 8 SMEM bank-groups ~uniformly at
// each loop position (order within a j's list is free: the sum commutes).
// Deterministic ranks via per-class ballots (no atomic ordering).
// ---------------------------------------------------------------------------
__global__ void k_compact(const float* __restrict__ w, const float* __restrict__ sigma,
                          const float* __restrict__ mu, const float* __restrict__ erev,
                          const float* __restrict__ mask,
                          const float* __restrict__ gleak, const float* __restrict__ vleak,
                          const float* __restrict__ cm,
                          const float* __restrict__ sw, const float* __restrict__ ssig,
                          const float* __restrict__ smu, const float* __restrict__ serev,
                          const float* __restrict__ smask) {
    int j = blockIdx.x, i = threadIdx.x;
    int lane = i & 31, wid = i >> 5;
    int x = i * NN + j;
    bool act = (mask[x] != 0.f);
    int key = ((i & 7) - (j & 7)) & 7;

    __shared__ int wcnt[8][8];     // [warp][class]
    __shared__ int base8[8];
    __shared__ int cnt_sh;
    __shared__ float swh[8], swe[8];

    // per-class ballots: deterministic in-warp rank + per-warp class counts
    int rank_w = 0;
    #pragma unroll
    for (int c = 0; c < 8; c++) {
        unsigned bal = __ballot_sync(0xFFFFFFFFu, act && key == c);
        if (lane == 0) wcnt[wid][c] = __popc(bal);
        if (act && key == c) rank_w = __popc(bal & ((1u << lane) - 1u));
    }

    // fused sensory table (threads 0..63 handle s = i for this j)
    if (i < SS) {
        int sidx = i * NN + j;
        float wsp = softplus_f(sw[sidx]) * smask[sidx];
        float a   = 0.5f * ssig[sidx];
        g_sparams[sidx] = make_float4(a, -a * smu[sidx], wsp * serev[sidx], wsp);
    }
    __syncthreads();

    if (i == 0) {
        int run = 0;
        #pragma unroll
        for (int c = 0; c < 8; c++) {
            base8[c] = run;
            int t = 0;
            #pragma unroll
            for (int w2 = 0; w2 < 8; w2++) t += wcnt[w2][c];
            run += t;
        }
        cnt_sh = run;
        atomicMax(&g_cntmax, run);
    }
    __syncthreads();
    int cnt = cnt_sh;

    float hw = 0.f, we = 0.f;
    if (act) {
        int before = 0;
        for (int w2 = 0; w2 < wid; w2++) before += wcnt[w2][key];
        int slot = base8[key] + before + rank_w;
        float a  = 0.5f * sigma[x];
        float b  = -a * mu[x];
        hw = 0.5f * softplus_f(w[x]);
        we = hw * erev[x];
        __half2 A  = __half2half2(__float2half_rn(a));
        __half2 Bv = __half2half2(__float2half_rn(b));
        __half2 W  = __half2half2(__float2half_rn(we));
        __half2 Wa = __half2half2(__float2half_rn(hw));
        uint4 pq;
        pq.x = *reinterpret_cast<unsigned*>(&A);
        pq.y = *reinterpret_cast<unsigned*>(&Bv);
        pq.z = *reinterpret_cast<unsigned*>(&W);
        pq.w = *reinterpret_cast<unsigned*>(&Wa);
        g_cpar[slot * NN + j]  = pq;
        g_cparf[slot * NN + j] = make_float4(a, b, we, hw);
        g_cidxT[j * CAP + slot] = (unsigned char)i;
    }

    // fused column sums: shfl-tree within warps, then 8-entry fold
    float rhw = hw, rwe = we;
    #pragma unroll
    for (int off = 16; off > 0; off >>= 1) {
        rhw += __shfl_down_sync(0xFFFFFFFFu, rhw, off);
        rwe += __shfl_down_sync(0xFFFFFFFFu, rwe, off);
    }
    if (lane == 0) { swh[wid] = rhw; swe[wid] = rwe; }

    // zero-pad remaining slots (contribute exactly 0)
    for (int s = cnt + i; s < CAP; s += NN) {
        g_cpar[s * NN + j]  = make_uint4(0u, 0u, 0u, 0u);
        g_cparf[s * NN + j] = make_float4(0.f, 0.f, 0.f, 0.f);
        g_cidxT[j * CAP + s] = 0;
    }
    __syncthreads();
    if (i == 0) {
        float shw = 0.f, shwe = 0.f;
        #pragma unroll
        for (int k = 0; k < 8; k++) { shw += swh[k]; shwe += swe[k]; }
        g_sum_hw[j]  = shw;
        g_sum_hwe[j] = shwe;
        float gl = softplus_f(gleak[j]);
        g_gl[j]  = gl;
        g_gv[j]  = gl * vleak[j];
        g_cmt[j] = softplus_f(cm[j]) * (float)UNFOLDS;
    }
}

// SMEM layout (dynamic)
#define SM_VFT  0                                // NN*8*4  = 8192 (f32 transposed state)
#define SM_VHT  (NN * 8 * 4)                     // NN*8*2  = 4096
#define SM_XIN  (SM_VHT + NN * 8 * 2)            // TB*SS*4 = 1792
#define SM_PART (SM_XIN + TB * SS * 4)           // 4*7*256*8 = 57344
#define SM_TOTAL (SM_PART + NGRP * TB * NN * 8)  // 71424

// ---------------------------------------------------------------------------
// Main: 147 CTAs x 1024 threads = 4 groups of 256 j-threads.
// Fast steps: group ig processes compacted slots [ig*2*nblk, (ig+1)*2*nblk)
// for ALL 7 batches via transposed v gathers (batch-paired f16x2 tanh),
// with one-block param prefetch. Final step: SAME slot list in fp32.
// nblk derived inline from g_cntmax (uniform across all threads).
// ---------------------------------------------------------------------------
__global__ void __launch_bounds__(1024, 1) k_main(const float* __restrict__ inputs,
                                                  const float* __restrict__ state,
                                                  float* __restrict__ out) {
    extern __shared__ char smem[];
    float*  v_fT           = reinterpret_cast<float*>(smem + SM_VFT);    // [NN][8]
    __half* v_hT           = reinterpret_cast<__half*>(smem + SM_VHT);   // [NN][8]
    float  (*xin)[SS]      = reinterpret_cast<float (*)[SS]>(smem + SM_XIN);
    float2 (*part)[TB][NN] = reinterpret_cast<float2 (*)[TB][NN]>(smem + SM_PART);

    int tid = threadIdx.x;
    int ig  = tid >> 8;          // 0..3
    int j   = tid & 255;
    int b0  = blockIdx.x * TB;
    int ob      = ig * 2;
    int own_cnt = (ig == 3) ? 1 : 2;

    if (tid < TB * SS) xin[tid >> 6][tid & 63] = inputs[min(b0 * SS + tid, BB * SS - 1)];
    for (int idx = tid; idx < TB * NN; idx += 1024) {
        float v = state[min(b0 * NN + idx, BB * NN - 1)];
        int bb = idx >> 8, jj = idx & 255;
        v_fT[jj * 8 + bb] = v;
        v_hT[jj * 8 + bb] = __float2half_rn(v);
    }
    if (tid < NN) {                       // pad batch 7
        v_fT[tid * 8 + 7] = 0.f;
        v_hT[tid * 8 + 7] = __float2half_rn(0.f);
    }
    __syncthreads();

    // --- sensory pass (step-invariant) for owned batches (<=2) ---
    float ncr[2], dcr[2];
    {
        float sn[2] = {0.f, 0.f}, sd[2] = {0.f, 0.f};
        #pragma unroll 2
        for (int s = 0; s < SS; s++) {
            float4 q = g_sparams[s * NN + j];
            #pragma unroll
            for (int k = 0; k < 2; k++) {
                int bx = ob + min(k, own_cnt - 1);
                float t  = tanh_fast(fmaf(q.x, xin[bx][s], q.y));
                float sg = fmaf(0.5f, t, 0.5f);
                sn[k] = fmaf(q.z, sg, sn[k]);
                sd[k] = fmaf(q.w, sg, sd[k]);
            }
        }
        float gv = g_gv[j], she = g_sum_hwe[j], gl = g_gl[j], shw = g_sum_hw[j];
        float cmt0 = g_cmt[j];
        #pragma unroll
        for (int k = 0; k < 2; k++) {
            ncr[k] = gv + she + sn[k];
            dcr[k] = cmt0 + gl + shw + sd[k] + 1e-8f;
        }
    }
    float cmt = g_cmt[j];

    // nblk computed inline (uniform): 2-slot blocks per group
    int nblk;
    {
        int c = g_cntmax;
        nblk = (c + NGRP * 2 - 1) / (NGRP * 2);
        if (nblk < 1) nblk = 1;
        if (nblk > BPG) nblk = BPG;
    }
    int sbase = ig * 2 * nblk;                // this group's first slot
    const unsigned char* CI = g_cidxT + j * CAP;
    const uint4*  CP  = g_cpar  + j;
    const float4* CPF = g_cparf + j;

    for (int step = 0; step < UNFOLDS; step++) {
        float numf[TB], denf[TB];
        #pragma unroll
        for (int b = 0; b < TB; b++) { numf[b] = 0.f; denf[b] = 0.f; }

        if (step < FAST_STEPS) {
            // ---------- sparse f16x2 path with one-block prefetch ----------
            unsigned num2[4] = {0u, 0u, 0u, 0u};
            unsigned den2[4] = {0u, 0u, 0u, 0u};
            uint4 p0 = CP[(sbase    ) * NN];
            uint4 p1 = CP[(sbase + 1) * NN];
            for (int blk = 0; blk < nblk; blk++) {
                int s0 = sbase + blk * 2;
                uchar2 ii = *reinterpret_cast<const uchar2*>(CI + s0);
                uint4 c0 = p0, c1 = p1;
                int sn = min(s0 + 2, CAP - 2);           // clamped prefetch
                p0 = CP[(sn    ) * NN];
                p1 = CP[(sn + 1) * NN];
                uint4 v0 = *reinterpret_cast<const uint4*>(v_hT + (int)ii.x * 8);
                uint4 v1 = *reinterpret_cast<const uint4*>(v_hT + (int)ii.y * 8);
                proc_slot2(v0, c0, num2, den2);
                proc_slot2(v1, c1, num2, den2);
                if ((blk & 1) || (blk == nblk - 1)) {
                    // fold 4-slot f16 partials to f32 (batch 7 = pad dropped)
                    fold2(num2[0], numf[0], numf[1]);
                    fold2(num2[1], numf[2], numf[3]);
                    fold2(num2[2], numf[4], numf[5]);
                    fold_lo(num2[3], numf[6]);
                    fold2(den2[0], denf[0], denf[1]);
                    fold2(den2[1], denf[2], denf[3]);
                    fold2(den2[2], denf[4], denf[5]);
                    fold_lo(den2[3], denf[6]);
                    #pragma unroll
                    for (int p = 0; p < 4; p++) { num2[p] = 0u; den2[p] = 0u; }
                }
            }
        } else {
            // ---------- sparse fp32 path (last step, same slot list) ----------
            for (int blk = 0; blk < nblk; blk++) {
                int s0 = sbase + blk * 2;
                uchar2 ii = *reinterpret_cast<const uchar2*>(CI + s0);
                #pragma unroll
                for (int h = 0; h < 2; h++) {
                    int slot = s0 + h;
                    int idx  = h ? (int)ii.y : (int)ii.x;
                    float4 pf = CPF[slot * NN];
                    float4 va = *reinterpret_cast<const float4*>(v_fT + idx * 8);
                    float4 vb = *reinterpret_cast<const float4*>(v_fT + idx * 8 + 4);
                    float t0 = tanh_fast(fmaf(pf.x, va.x, pf.y));
                    float t1 = tanh_fast(fmaf(pf.x, va.y, pf.y));
                    float t2 = tanh_fast(fmaf(pf.x, va.z, pf.y));
                    float t3 = tanh_fast(fmaf(pf.x, va.w, pf.y));
                    float t4 = tanh_fast(fmaf(pf.x, vb.x, pf.y));
                    float t5 = tanh_fast(fmaf(pf.x, vb.y, pf.y));
                    float t6 = tanh_fast(fmaf(pf.x, vb.z, pf.y));
                    numf[0] = fmaf(pf.z, t0, numf[0]); denf[0] = fmaf(pf.w, t0, denf[0]);
                    numf[1] = fmaf(pf.z, t1, numf[1]); denf[1] = fmaf(pf.w, t1, denf[1]);
                    numf[2] = fmaf(pf.z, t2, numf[2]); denf[2] = fmaf(pf.w, t2, denf[2]);
                    numf[3] = fmaf(pf.z, t3, numf[3]); denf[3] = fmaf(pf.w, t3, denf[3]);
                    numf[4] = fmaf(pf.z, t4, numf[4]); denf[4] = fmaf(pf.w, t4, denf[4]);
                    numf[5] = fmaf(pf.z, t5, numf[5]); denf[5] = fmaf(pf.w, t5, denf[5]);
                    numf[6] = fmaf(pf.z, t6, numf[6]); denf[6] = fmaf(pf.w, t6, denf[6]);
                }
            }
        }

        #pragma unroll
        for (int b = 0; b < TB; b++)
            part[ig][b][j] = make_float2(numf[b], denf[b]);
        __syncthreads();

        #pragma unroll
        for (int k = 0; k < 2; k++) {
            if (k < own_cnt) {
                int b = ob + k;
                float2 p0 = part[0][b][j];
                float2 p1 = part[1][b][j];
                float2 p2 = part[2][b][j];
                float2 p3 = part[3][b][j];
                float n = (p0.x + p1.x) + (p2.x + p3.x);
                float d = (p0.y + p1.y) + (p2.y + p3.y);
                float vn = (fmaf(cmt, v_fT[j * 8 + b], ncr[k]) + n) / (d + dcr[k]);
                v_fT[j * 8 + b] = vn;
                v_hT[j * 8 + b] = __float2half_rn(vn);
            }
        }
        __syncthreads();
    }

    #pragma unroll
    for (int k = 0; k < 2; k++) {
        if (k < own_cnt) {
            int b = ob + k;
            if (b0 + b < BB) out[(b0 + b) * NN + j] = v_fT[j * 8 + b];
        }
    }
}

extern "C" void kernel_launch(void* const* d_in, const int* in_sizes, int n_in,
                              void* d_out, int out_size) {
    const float* inputs = (const float*)d_in[0];
    const float* state  = (const float*)d_in[1];
    const float* gleak  = (const float*)d_in[2];
    const float* vleak  = (const float*)d_in[3];
    const float* cm     = (const float*)d_in[4];
    const float* w      = (const float*)d_in[5];
    const float* sigma  = (const float*)d_in[6];
    const float* mu     = (const float*)d_in[7];
    const float* erev   = (const float*)d_in[8];
    const float* sw     = (const float*)d_in[9];
    const float* ssig   = (const float*)d_in[10];
    const float* smu    = (const float*)d_in[11];
    const float* serev  = (const float*)d_in[12];
    const float* mask   = (const float*)d_in[13];
    const float* smask  = (const float*)d_in[14];
    float* out = (float*)d_out;

    cudaFuncSetAttribute(k_main, cudaFuncAttributeMaxDynamicSharedMemorySize, SM_TOTAL);

    k_compact<<<NN, NN>>>(w, sigma, mu, erev, mask, gleak, vleak, cm,
                          sw, ssig, smu, serev, smask);
    k_main   <<<GRID, 1024, SM_TOTAL>>>(inputs, state, out);
}

// round 17
// speedup vs baseline: 1.1891x; 1.1004x over previous
#include <cuda_runtime.h>
#include <cuda_fp16.h>

#define NN 256
#define SS 64
#define BB 1024
#define UNFOLDS 12
#define FAST_STEPS 11          // steps 0..10 sparse f16x2; step 11 sparse fp32
#define TB 7                   // batches per CTA (147 CTAs cover 1024 with clamp)
#define GRID 147
#define NGRP 4                 // groups per CTA
#define CAP 192                // compacted-slot capacity per j
#define BPG (CAP / (NGRP * 2)) // max 2-slot blocks per group

// Scratch (device globals — no allocations allowed).
__device__ uint2  g_cp8[CAP * NN];          // [slot][j] {(a,b) half2, (we,|we|) half2} 8 B
__device__ float4 g_cparf[CAP * NN];        // [slot][j] {a, b, we, |we|} f32 (closing step)
__device__ unsigned short g_cidx2[(CAP / 2) * NN]; // [slot/2][j] packed index pair (slot-major!)
__device__ int    g_cntmax;                 // max active count over j
__device__ float4 g_sparams[SS * NN];       // sensory {a, b, we, wsp} f32
__device__ float  g_sum_hw[NN];
__device__ float  g_sum_hwe[NN];
__device__ float  g_cmt[NN];
__device__ float  g_gl[NN];
__device__ float  g_gv[NN];

__device__ __forceinline__ float tanh_fast(float x) {
    float t;
    asm("tanh.approx.f32 %0, %1;" : "=f"(t) : "f"(x));
    return t;
}

__device__ __forceinline__ float softplus_f(float x) {
    return log1pf(expf(x));
}

__device__ __forceinline__ unsigned prmt(unsigned v, unsigned sel) {
    unsigned r;
    asm("prmt.b32 %0, %1, %1, %2;" : "=r"(r) : "r"(v), "r"(sel));
    return r;
}

// One compacted slot: params arrive packed {a,b} / {we,wa}; duplicate halves
// in-register (PRMT), then batch-pairs (01,23,45,6pad):
//   arg2 = a2dup*vpair + b2dup (HFMA2); t = tanh.f16x2 (2 batches per XU op)
//   num2[p] += we2dup*t ; den2[p] += wa2dup*t (f16 partials, folded every 4 slots)
__device__ __forceinline__ void proc_slot8(uint4 vv, uint2 pk,
                                           unsigned* num2, unsigned* den2) {
    unsigned a2 = prmt(pk.x, 0x1010u);   // lo half (a) duplicated
    unsigned b2 = prmt(pk.x, 0x3232u);   // hi half (b) duplicated
    unsigned w2 = prmt(pk.y, 0x1010u);   // we duplicated
    unsigned x2 = prmt(pk.y, 0x3232u);   // |we| duplicated
    unsigned a, t;
    asm("fma.rn.f16x2 %0, %1, %2, %3;" : "=r"(a) : "r"(a2), "r"(vv.x), "r"(b2));
    asm("tanh.approx.f16x2 %0, %1;" : "=r"(t) : "r"(a));
    asm("fma.rn.f16x2 %0, %1, %2, %0;" : "+r"(num2[0]) : "r"(w2), "r"(t));
    asm("fma.rn.f16x2 %0, %1, %2, %0;" : "+r"(den2[0]) : "r"(x2), "r"(t));
    asm("fma.rn.f16x2 %0, %1, %2, %3;" : "=r"(a) : "r"(a2), "r"(vv.y), "r"(b2));
    asm("tanh.approx.f16x2 %0, %1;" : "=r"(t) : "r"(a));
    asm("fma.rn.f16x2 %0, %1, %2, %0;" : "+r"(num2[1]) : "r"(w2), "r"(t));
    asm("fma.rn.f16x2 %0, %1, %2, %0;" : "+r"(den2[1]) : "r"(x2), "r"(t));
    asm("fma.rn.f16x2 %0, %1, %2, %3;" : "=r"(a) : "r"(a2), "r"(vv.z), "r"(b2));
    asm("tanh.approx.f16x2 %0, %1;" : "=r"(t) : "r"(a));
    asm("fma.rn.f16x2 %0, %1, %2, %0;" : "+r"(num2[2]) : "r"(w2), "r"(t));
    asm("fma.rn.f16x2 %0, %1, %2, %0;" : "+r"(den2[2]) : "r"(x2), "r"(t));
    asm("fma.rn.f16x2 %0, %1, %2, %3;" : "=r"(a) : "r"(a2), "r"(vv.w), "r"(b2));
    asm("tanh.approx.f16x2 %0, %1;" : "=r"(t) : "r"(a));
    asm("fma.rn.f16x2 %0, %1, %2, %0;" : "+r"(num2[3]) : "r"(w2), "r"(t));
    asm("fma.rn.f16x2 %0, %1, %2, %0;" : "+r"(den2[3]) : "r"(x2), "r"(t));
}

__device__ __forceinline__ void fold2(unsigned h2, float& alo, float& ahi) {
    float lo, hi;
    asm("{ .reg .b16 l, h;\n\t"
        "  mov.b32 {l, h}, %2;\n\t"
        "  cvt.f32.f16 %0, l;\n\t"
        "  cvt.f32.f16 %1, h; }"
        : "=f"(lo), "=f"(hi) : "r"(h2));
    alo += lo;
    ahi += hi;
}
__device__ __forceinline__ void fold_lo(unsigned h2, float& alo) {
    float lo;
    asm("{ .reg .b16 l, h;\n\t"
        "  mov.b32 {l, h}, %1;\n\t"
        "  cvt.f32.f16 %0, l; }"
        : "=f"(lo) : "r"(h2));
    alo += lo;
}

// ---------------------------------------------------------------------------
// Parallel per-j compaction with bank-group scheduling + fused column sums,
// per-neuron scalars, and sensory table. One block per j.
// Slots ordered by key = ((i&7) - (j&7)) & 7 so warp lanes spread over all 8
// SMEM bank-groups in k_main's gather. Indices packed slot-major for
// coalesced k_main loads.
// ---------------------------------------------------------------------------
__global__ void k_compact(const float* __restrict__ w, const float* __restrict__ sigma,
                          const float* __restrict__ mu, const float* __restrict__ erev,
                          const float* __restrict__ mask,
                          const float* __restrict__ gleak, const float* __restrict__ vleak,
                          const float* __restrict__ cm,
                          const float* __restrict__ sw, const float* __restrict__ ssig,
                          const float* __restrict__ smu, const float* __restrict__ serev,
                          const float* __restrict__ smask) {
    int j = blockIdx.x, i = threadIdx.x;
    int lane = i & 31, wid = i >> 5;
    int x = i * NN + j;
    bool act = (mask[x] != 0.f);
    int key = ((i & 7) - (j & 7)) & 7;

    __shared__ int wcnt[8][8];     // [warp][class]
    __shared__ int base8[8];
    __shared__ int cnt_sh;
    __shared__ float swh[8], swe[8];
    __shared__ unsigned char idx_sh[CAP];

    // per-class ballots: deterministic in-warp rank + per-warp class counts
    int rank_w = 0;
    #pragma unroll
    for (int c = 0; c < 8; c++) {
        unsigned bal = __ballot_sync(0xFFFFFFFFu, act && key == c);
        if (lane == 0) wcnt[wid][c] = __popc(bal);
        if (act && key == c) rank_w = __popc(bal & ((1u << lane) - 1u));
    }

    // fused sensory table (threads 0..63 handle s = i for this j)
    if (i < SS) {
        int sidx = i * NN + j;
        float wsp = softplus_f(sw[sidx]) * smask[sidx];
        float a   = 0.5f * ssig[sidx];
        g_sparams[sidx] = make_float4(a, -a * smu[sidx], wsp * serev[sidx], wsp);
    }
    __syncthreads();

    if (i == 0) {
        int run = 0;
        #pragma unroll
        for (int c = 0; c < 8; c++) {
            base8[c] = run;
            int t = 0;
            #pragma unroll
            for (int w2 = 0; w2 < 8; w2++) t += wcnt[w2][c];
            run += t;
        }
        cnt_sh = run;
        atomicMax(&g_cntmax, run);
    }
    __syncthreads();
    int cnt = cnt_sh;

    float hw = 0.f, we = 0.f;
    if (act) {
        int before = 0;
        for (int w2 = 0; w2 < wid; w2++) before += wcnt[w2][key];
        int slot = base8[key] + before + rank_w;
        float a  = 0.5f * sigma[x];
        float b  = -a * mu[x];
        hw = 0.5f * softplus_f(w[x]);
        we = hw * erev[x];
        __half2 AB = __floats2half2_rn(a, b);
        __half2 WX = __floats2half2_rn(we, hw);
        uint2 pk;
        pk.x = *reinterpret_cast<unsigned*>(&AB);
        pk.y = *reinterpret_cast<unsigned*>(&WX);
        g_cp8[slot * NN + j]   = pk;
        g_cparf[slot * NN + j] = make_float4(a, b, we, hw);
        idx_sh[slot] = (unsigned char)i;
    }

    // fused column sums: shfl-tree within warps, then 8-entry fold
    float rhw = hw, rwe = we;
    #pragma unroll
    for (int off = 16; off > 0; off >>= 1) {
        rhw += __shfl_down_sync(0xFFFFFFFFu, rhw, off);
        rwe += __shfl_down_sync(0xFFFFFFFFu, rwe, off);
    }
    if (lane == 0) { swh[wid] = rhw; swe[wid] = rwe; }

    // zero-pad remaining slots (contribute exactly 0)
    for (int s = cnt + i; s < CAP; s += NN) {
        g_cp8[s * NN + j]   = make_uint2(0u, 0u);
        g_cparf[s * NN + j] = make_float4(0.f, 0.f, 0.f, 0.f);
        idx_sh[s] = 0;
    }
    __syncthreads();

    // pack index pairs slot-major for coalesced k_main loads
    if (i < CAP / 2)
        g_cidx2[i * NN + j] =
            (unsigned short)(idx_sh[2 * i] | ((unsigned short)idx_sh[2 * i + 1] << 8));

    if (i == 0) {
        float shw = 0.f, shwe = 0.f;
        #pragma unroll
        for (int k = 0; k < 8; k++) { shw += swh[k]; shwe += swe[k]; }
        g_sum_hw[j]  = shw;
        g_sum_hwe[j] = shwe;
        float gl = softplus_f(gleak[j]);
        g_gl[j]  = gl;
        g_gv[j]  = gl * vleak[j];
        g_cmt[j] = softplus_f(cm[j]) * (float)UNFOLDS;
    }
}

// SMEM layout (dynamic)
#define SM_VFT  0                                // NN*8*4  = 8192 (f32 transposed state)
#define SM_VHT  (NN * 8 * 4)                     // NN*8*2  = 4096
#define SM_XIN  (SM_VHT + NN * 8 * 2)            // TB*SS*4 = 1792
#define SM_PART (SM_XIN + TB * SS * 4)           // 4*7*256*8 = 57344
#define SM_TOTAL (SM_PART + NGRP * TB * NN * 8)  // 71424

// ---------------------------------------------------------------------------
// Main: 147 CTAs x 1024 threads = 4 groups of 256 j-threads.
// Fast steps: group ig processes compacted slots [ig*2*nblk, (ig+1)*2*nblk)
// for ALL 7 batches via transposed v gathers (batch-paired f16x2 tanh),
// 8-byte param loads + coalesced index pairs. Final step: same list, fp32.
// ---------------------------------------------------------------------------
__global__ void __launch_bounds__(1024, 1) k_main(const float* __restrict__ inputs,
                                                  const float* __restrict__ state,
                                                  float* __restrict__ out) {
    extern __shared__ char smem[];
    float*  v_fT           = reinterpret_cast<float*>(smem + SM_VFT);    // [NN][8]
    __half* v_hT           = reinterpret_cast<__half*>(smem + SM_VHT);   // [NN][8]
    float  (*xin)[SS]      = reinterpret_cast<float (*)[SS]>(smem + SM_XIN);
    float2 (*part)[TB][NN] = reinterpret_cast<float2 (*)[TB][NN]>(smem + SM_PART);

    int tid = threadIdx.x;
    int ig  = tid >> 8;          // 0..3
    int j   = tid & 255;
    int b0  = blockIdx.x * TB;
    int ob      = ig * 2;
    int own_cnt = (ig == 3) ? 1 : 2;

    if (tid < TB * SS) xin[tid >> 6][tid & 63] = inputs[min(b0 * SS + tid, BB * SS - 1)];
    for (int idx = tid; idx < TB * NN; idx += 1024) {
        float v = state[min(b0 * NN + idx, BB * NN - 1)];
        int bb = idx >> 8, jj = idx & 255;
        v_fT[jj * 8 + bb] = v;
        v_hT[jj * 8 + bb] = __float2half_rn(v);
    }
    if (tid < NN) {                       // pad batch 7
        v_fT[tid * 8 + 7] = 0.f;
        v_hT[tid * 8 + 7] = __float2half_rn(0.f);
    }
    __syncthreads();

    // --- sensory pass (step-invariant) for owned batches (<=2) ---
    float ncr[2], dcr[2];
    {
        float sn[2] = {0.f, 0.f}, sd[2] = {0.f, 0.f};
        #pragma unroll 2
        for (int s = 0; s < SS; s++) {
            float4 q = g_sparams[s * NN + j];
            #pragma unroll
            for (int k = 0; k < 2; k++) {
                int bx = ob + min(k, own_cnt - 1);
                float t  = tanh_fast(fmaf(q.x, xin[bx][s], q.y));
                float sg = fmaf(0.5f, t, 0.5f);
                sn[k] = fmaf(q.z, sg, sn[k]);
                sd[k] = fmaf(q.w, sg, sd[k]);
            }
        }
        float gv = g_gv[j], she = g_sum_hwe[j], gl = g_gl[j], shw = g_sum_hw[j];
        float cmt0 = g_cmt[j];
        #pragma unroll
        for (int k = 0; k < 2; k++) {
            ncr[k] = gv + she + sn[k];
            dcr[k] = cmt0 + gl + shw + sd[k] + 1e-8f;
        }
    }
    float cmt = g_cmt[j];

    // nblk computed inline (uniform): 2-slot blocks per group
    int nblk;
    {
        int c = g_cntmax;
        nblk = (c + NGRP * 2 - 1) / (NGRP * 2);
        if (nblk < 1) nblk = 1;
        if (nblk > BPG) nblk = BPG;
    }
    int sbase = ig * 2 * nblk;                // this group's first slot (even)
    const unsigned short* CI2 = g_cidx2 + j;
    const uint2*  CP  = g_cp8   + j;
    const float4* CPF = g_cparf + j;

    for (int step = 0; step < UNFOLDS; step++) {
        float numf[TB], denf[TB];
        #pragma unroll
        for (int b = 0; b < TB; b++) { numf[b] = 0.f; denf[b] = 0.f; }

        if (step < FAST_STEPS) {
            // ---------- sparse f16x2 path with one-block prefetch ----------
            unsigned num2[4] = {0u, 0u, 0u, 0u};
            unsigned den2[4] = {0u, 0u, 0u, 0u};
            uint2 p0 = CP[(sbase    ) * NN];
            uint2 p1 = CP[(sbase + 1) * NN];
            for (int blk = 0; blk < nblk; blk++) {
                int s0 = sbase + blk * 2;
                unsigned short ii = CI2[(s0 >> 1) * NN];   // coalesced pair load
                uint2 c0 = p0, c1 = p1;
                int sn = min(s0 + 2, CAP - 2);             // clamped prefetch
                p0 = CP[(sn    ) * NN];
                p1 = CP[(sn + 1) * NN];
                uint4 v0 = *reinterpret_cast<const uint4*>(v_hT + (int)(ii & 255u) * 8);
                uint4 v1 = *reinterpret_cast<const uint4*>(v_hT + (int)(ii >> 8) * 8);
                proc_slot8(v0, c0, num2, den2);
                proc_slot8(v1, c1, num2, den2);
                if ((blk & 1) || (blk == nblk - 1)) {
                    // fold 4-slot f16 partials to f32 (batch 7 = pad dropped)
                    fold2(num2[0], numf[0], numf[1]);
                    fold2(num2[1], numf[2], numf[3]);
                    fold2(num2[2], numf[4], numf[5]);
                    fold_lo(num2[3], numf[6]);
                    fold2(den2[0], denf[0], denf[1]);
                    fold2(den2[1], denf[2], denf[3]);
                    fold2(den2[2], denf[4], denf[5]);
                    fold_lo(den2[3], denf[6]);
                    #pragma unroll
                    for (int p = 0; p < 4; p++) { num2[p] = 0u; den2[p] = 0u; }
                }
            }
        } else {
            // ---------- sparse fp32 path (last step, same slot list) ----------
            for (int blk = 0; blk < nblk; blk++) {
                int s0 = sbase + blk * 2;
                unsigned short ii = CI2[(s0 >> 1) * NN];
                #pragma unroll
                for (int h = 0; h < 2; h++) {
                    int slot = s0 + h;
                    int idx  = h ? (int)(ii >> 8) : (int)(ii & 255u);
                    float4 pf = CPF[slot * NN];
                    float4 va = *reinterpret_cast<const float4*>(v_fT + idx * 8);
                    float4 vb = *reinterpret_cast<const float4*>(v_fT + idx * 8 + 4);
                    float t0 = tanh_fast(fmaf(pf.x, va.x, pf.y));
                    float t1 = tanh_fast(fmaf(pf.x, va.y, pf.y));
                    float t2 = tanh_fast(fmaf(pf.x, va.z, pf.y));
                    float t3 = tanh_fast(fmaf(pf.x, va.w, pf.y));
                    float t4 = tanh_fast(fmaf(pf.x, vb.x, pf.y));
                    float t5 = tanh_fast(fmaf(pf.x, vb.y, pf.y));
                    float t6 = tanh_fast(fmaf(pf.x, vb.z, pf.y));
                    numf[0] = fmaf(pf.z, t0, numf[0]); denf[0] = fmaf(pf.w, t0, denf[0]);
                    numf[1] = fmaf(pf.z, t1, numf[1]); denf[1] = fmaf(pf.w, t1, denf[1]);
                    numf[2] = fmaf(pf.z, t2, numf[2]); denf[2] = fmaf(pf.w, t2, denf[2]);
                    numf[3] = fmaf(pf.z, t3, numf[3]); denf[3] = fmaf(pf.w, t3, denf[3]);
                    numf[4] = fmaf(pf.z, t4, numf[4]); denf[4] = fmaf(pf.w, t4, denf[4]);
                    numf[5] = fmaf(pf.z, t5, numf[5]); denf[5] = fmaf(pf.w, t5, denf[5]);
                    numf[6] = fmaf(pf.z, t6, numf[6]); denf[6] = fmaf(pf.w, t6, denf[6]);
                }
            }
        }

        #pragma unroll
        for (int b = 0; b < TB; b++)
            part[ig][b][j] = make_float2(numf[b], denf[b]);
        __syncthreads();

        #pragma unroll
        for (int k = 0; k < 2; k++) {
            if (k < own_cnt) {
                int b = ob + k;
                float2 p0 = part[0][b][j];
                float2 p1 = part[1][b][j];
                float2 p2 = part[2][b][j];
                float2 p3 = part[3][b][j];
                float n = (p0.x + p1.x) + (p2.x + p3.x);
                float d = (p0.y + p1.y) + (p2.y + p3.y);
                float vn = (fmaf(cmt, v_fT[j * 8 + b], ncr[k]) + n) / (d + dcr[k]);
                v_fT[j * 8 + b] = vn;
                v_hT[j * 8 + b] = __float2half_rn(vn);
            }
        }
        __syncthreads();
    }

    #pragma unroll
    for (int k = 0; k < 2; k++) {
        if (k < own_cnt) {
            int b = ob + k;
            if (b0 + b < BB) out[(b0 + b) * NN + j] = v_fT[j * 8 + b];
        }
    }
}

extern "C" void kernel_launch(void* const* d_in, const int* in_sizes, int n_in,
                              void* d_out, int out_size) {
    const float* inputs = (const float*)d_in[0];
    const float* state  = (const float*)d_in[1];
    const float* gleak  = (const float*)d_in[2];
    const float* vleak  = (const float*)d_in[3];
    const float* cm     = (const float*)d_in[4];
    const float* w      = (const float*)d_in[5];
    const float* sigma  = (const float*)d_in[6];
    const float* mu     = (const float*)d_in[7];
    const float* erev   = (const float*)d_in[8];
    const float* sw     = (const float*)d_in[9];
    const float* ssig   = (const float*)d_in[10];
    const float* smu    = (const float*)d_in[11];
    const float* serev  = (const float*)d_in[12];
    const float* mask   = (const float*)d_in[13];
    const float* smask  = (const float*)d_in[14];
    float* out = (float*)d_out;

    cudaFuncSetAttribute(k_main, cudaFuncAttributeMaxDynamicSharedMemorySize, SM_TOTAL);

    k_compact<<<NN, NN>>>(w, sigma, mu, erev, mask, gleak, vleak, cm,
                          sw, ssig, smu, serev, smask);
    k_main   <<<GRID, 1024, SM_TOTAL>>>(inputs, state, out);
}